// round 14
// baseline (speedup 1.0000x reference)
#include <cuda_runtime.h>
#include <cuda_bf16.h>
#include <math.h>
#include <stdint.h>

#define DM 512
#define NH 8
#define DH 64
#define LQn 2048
#define LKn 4096
#define BSZ 2

#define BQ 64
#define BK 64
#define NT (LKn / BK)

// Scratch (allocation-free): projected Q/K/V and attention output, all fp32.
__device__ float g_Qp[(size_t)BSZ * LQn * DM];
__device__ float g_Kp[(size_t)BSZ * LKn * DM];
__device__ float g_Vp[(size_t)BSZ * LKn * DM];
__device__ float g_AO[(size_t)BSZ * LQn * DM];

// ---------------------------------------------------------------------------
// MMA + packing primitives
// ---------------------------------------------------------------------------
__device__ __forceinline__ void mma_tf32(float c[4], const uint32_t a[4],
                                         uint32_t b0, uint32_t b1) {
    asm volatile(
        "mma.sync.aligned.m16n8k8.row.col.f32.tf32.tf32.f32 "
        "{%0,%1,%2,%3}, {%4,%5,%6,%7}, {%8,%9}, {%0,%1,%2,%3};"
        : "+f"(c[0]), "+f"(c[1]), "+f"(c[2]), "+f"(c[3])
        : "r"(a[0]), "r"(a[1]), "r"(a[2]), "r"(a[3]), "r"(b0), "r"(b1));
}

__device__ __forceinline__ void mma_bf16(float c[4], const uint32_t a[4],
                                         uint32_t b0, uint32_t b1) {
    asm volatile(
        "mma.sync.aligned.m16n8k16.row.col.f32.bf16.bf16.f32 "
        "{%0,%1,%2,%3}, {%4,%5,%6,%7}, {%8,%9}, {%0,%1,%2,%3};"
        : "+f"(c[0]), "+f"(c[1]), "+f"(c[2]), "+f"(c[3])
        : "r"(a[0]), "r"(a[1]), "r"(a[2]), "r"(a[3]), "r"(b0), "r"(b1));
}

__device__ __forceinline__ uint32_t cvt_tf32(float f) {
    uint32_t u;
    asm("cvt.rna.tf32.f32 %0, %1;" : "=r"(u) : "f"(f));
    return u;
}

__device__ __forceinline__ void pack_bf16_hilo(float f0, float f1,
                                               uint32_t& hi, uint32_t& lo) {
    asm("cvt.rn.bf16x2.f32 %0, %1, %2;" : "=r"(hi) : "f"(f1), "f"(f0));
    float h0 = __uint_as_float(hi << 16);
    float h1 = __uint_as_float(hi & 0xffff0000u);
    float r0 = f0 - h0, r1 = f1 - h1;
    asm("cvt.rn.bf16x2.f32 %0, %1, %2;" : "=r"(lo) : "f"(r1), "f"(r0));
}

__device__ __forceinline__ void cp_async16(uint32_t dst, const void* src) {
    asm volatile("cp.async.ca.shared.global [%0], [%1], 16;"
                 :: "r"(dst), "l"(src));
}
__device__ __forceinline__ void cp_commit() {
    asm volatile("cp.async.commit_group;");
}
__device__ __forceinline__ void cp_wait_all() {
    asm volatile("cp.async.wait_group 0;");
}

// ---------------------------------------------------------------------------
// Tensor-core GEMM: C[M,512] = A[M,512] @ W[512,512]^T + bias
// bf16 3-term hi/lo split. CTA: 256 threads / 8 warps; tile 128x64.
// ---------------------------------------------------------------------------
#define GS 20   // uint32 stride of packed-k rows (16 used + 4 pad)

__global__ __launch_bounds__(256)
void gemm_bf16_kernel(const float* __restrict__ A,
                      const float* __restrict__ W,
                      const float* __restrict__ bias,
                      float* __restrict__ C, int M) {
    __shared__ uint32_t AsH[128 * GS], AsL[128 * GS];
    __shared__ uint32_t WsH[64 * GS],  WsL[64 * GS];

    const int tid = threadIdx.x;
    const int lane = tid & 31, warp = tid >> 5;
    const int qr = lane >> 2, qc = lane & 3;
    const int n0 = blockIdx.x * 64, m0 = blockIdx.y * 128;

    float acc[8][4];
    #pragma unroll
    for (int nb = 0; nb < 8; nb++)
        #pragma unroll
        for (int i = 0; i < 4; i++) acc[nb][i] = 0.0f;

    for (int k0 = 0; k0 < DM; k0 += 32) {
        __syncthreads();
        // A slab: 128 rows x 32 k
        #pragma unroll
        for (int p = 0; p < 4; p++) {
            int idx = tid + p * 256;
            int r = idx >> 3, fg = idx & 7;
            float4 av = *(const float4*)(A + (size_t)(m0 + r) * DM + k0 + fg * 4);
            uint32_t h0, l0, h1, l1;
            pack_bf16_hilo(av.x, av.y, h0, l0);
            pack_bf16_hilo(av.z, av.w, h1, l1);
            AsH[r * GS + fg * 2] = h0; AsH[r * GS + fg * 2 + 1] = h1;
            AsL[r * GS + fg * 2] = l0; AsL[r * GS + fg * 2 + 1] = l1;
        }
        // W slab: 64 rows x 32 k
        #pragma unroll
        for (int p = 0; p < 2; p++) {
            int idx = tid + p * 256;
            int r = idx >> 3, fg = idx & 7;
            float4 wv = *(const float4*)(W + (size_t)(n0 + r) * DM + k0 + fg * 4);
            uint32_t h0, l0, h1, l1;
            pack_bf16_hilo(wv.x, wv.y, h0, l0);
            pack_bf16_hilo(wv.z, wv.w, h1, l1);
            WsH[r * GS + fg * 2] = h0; WsH[r * GS + fg * 2 + 1] = h1;
            WsL[r * GS + fg * 2] = l0; WsL[r * GS + fg * 2 + 1] = l1;
        }
        __syncthreads();

        uint32_t ahH[2][4], ahL[2][4];
        #pragma unroll
        for (int kb = 0; kb < 2; kb++) {
            int base = (16 * warp + qr) * GS + kb * 8 + qc;
            ahH[kb][0] = AsH[base];     ahH[kb][1] = AsH[base + 8 * GS];
            ahH[kb][2] = AsH[base + 4]; ahH[kb][3] = AsH[base + 8 * GS + 4];
            ahL[kb][0] = AsL[base];     ahL[kb][1] = AsL[base + 8 * GS];
            ahL[kb][2] = AsL[base + 4]; ahL[kb][3] = AsL[base + 8 * GS + 4];
        }

        #pragma unroll
        for (int nb = 0; nb < 8; nb++) {
            #pragma unroll
            for (int kb = 0; kb < 2; kb++) {
                int wb = (8 * nb + qr) * GS + kb * 8 + qc;
                uint32_t bh0 = WsH[wb], bh1 = WsH[wb + 4];
                uint32_t bl0 = WsL[wb], bl1 = WsL[wb + 4];
                mma_bf16(acc[nb], ahH[kb], bh0, bh1);
                mma_bf16(acc[nb], ahL[kb], bh0, bh1);
                mma_bf16(acc[nb], ahH[kb], bl0, bl1);
            }
        }
    }

    const int row0 = m0 + 16 * warp + qr;
    #pragma unroll
    for (int nb = 0; nb < 8; nb++) {
        int n = n0 + 8 * nb + 2 * qc;
        float2 bv = *(const float2*)(bias + n);
        float2 c01 = make_float2(acc[nb][0] + bv.x, acc[nb][1] + bv.y);
        float2 c23 = make_float2(acc[nb][2] + bv.x, acc[nb][3] + bv.y);
        *(float2*)(C + (size_t)row0 * DM + n) = c01;
        *(float2*)(C + (size_t)(row0 + 8) * DM + n) = c23;
    }
}

// ---------------------------------------------------------------------------
// Tensor-core flash attention, 2-stage pipelined.
//   S = Q K^T : tf32 MMA. K staged raw fp32 via cp.async (XOR-swizzled 16B
//               chunks, conflict-free B-frag LDS.32), cvt.rna at consume.
//   P V      : tf32 MMA with permuted-k trick: S C-frag == PV A-frag
//               (a = {c0,c2,c1,c3}), B-frag = adjacent key pair -> LDS.64
//               from swizzled V^T (conflict-free).
// Dynamic smem: Ks[2][64*64] + Vt[2][64*64] fp32/tf32 + gsm[2][64] = 66048 B.
// ---------------------------------------------------------------------------
#define ATTN_SMEM 66048

__global__ __launch_bounds__(128, 2)
void attn_kernel(const float* __restrict__ gate, const int* __restrict__ mask) {
    extern __shared__ uint32_t sm[];
    uint32_t* KsS[2] = { sm, sm + 4096 };            // raw fp32 K, swizzled
    uint32_t* VtS[2] = { sm + 8192, sm + 12288 };    // tf32 V^T, swizzled
    float*    gsmP   = (float*)(sm + 16384);         // [2][64]

    const int tid = threadIdx.x;
    const int lane = tid & 31, warp = tid >> 5;
    const int qr = lane >> 2;       // 0..7
    const int qc = lane & 3;        // 0..3
    const int r0 = warp * 16;

    const int q0 = blockIdx.x * BQ;
    const int h = blockIdx.y, b = blockIdx.z;

    const float* Qb = g_Qp + ((size_t)b * LQn + q0) * DM + h * DH;
    const float* Kb = g_Kp + (size_t)b * LKn * DM + h * DH;
    const float* Vb = g_Vp + (size_t)b * LKn * DM + h * DH;
    const float* gb = gate + (size_t)b * LKn;
    const int*   mb = mask + (size_t)b * LKn;

    uint32_t ks_base[2];
    ks_base[0] = (uint32_t)__cvta_generic_to_shared(KsS[0]);
    ks_base[1] = (uint32_t)__cvta_generic_to_shared(KsS[1]);

    // ================= prologue =================
    // tile 0: K via cp.async into stage 0
    #pragma unroll
    for (int p = 0; p < 8; p++) {
        int id = tid + p * 128;
        int r = id >> 4, ch = id & 15;
        cp_async16(ks_base[0] + r * 256 + ((ch ^ (r & 7)) << 4),
                   Kb + (size_t)r * DM + ch * 4);
    }
    cp_commit();

    // tile 0: V -> regs (key-spread mapping: 8 keys x 4 d-groups per warp-iter)
    float4 vreg[8];
    #pragma unroll
    for (int p = 0; p < 8; p++) {
        int bi = warp + 4 * p;
        int key = (bi & 7) * 8 + (lane & 7);
        int dgrp = (bi >> 3) * 4 + (lane >> 3);
        vreg[p] = *(const float4*)(Vb + (size_t)key * DM + dgrp * 4);
    }
    float gnv = 0.0f; int mnv = 0;
    if (tid < 64) { gnv = gb[tid]; mnv = mb[tid]; }

    // Q tile -> stage-1 K buffer (raw fp32, same swizzle) for frag extraction
    #pragma unroll
    for (int p = 0; p < 8; p++) {
        int id = tid + p * 128;
        int r = id >> 4, ch = id & 15;
        float4 v = *(const float4*)(Qb + (size_t)r * DM + ch * 4);
        *(float4*)&KsS[1][r * 64 + ((ch ^ (r & 7)) << 2)] = v;
    }
    __syncthreads();

    uint32_t qa[8][4];   // Q A-fragments (tf32, scale 1/8 folded), persistent
    {
        const float* Q1 = (const float*)KsS[1];
        #pragma unroll
        for (int kb = 0; kb < 8; kb++) {
            int c0 = ((2 * kb) ^ qr) * 4 + qc;
            int c1 = ((2 * kb + 1) ^ qr) * 4 + qc;
            qa[kb][0] = cvt_tf32(Q1[(r0 + qr) * 64 + c0] * 0.125f);
            qa[kb][1] = cvt_tf32(Q1[(r0 + qr + 8) * 64 + c0] * 0.125f);
            qa[kb][2] = cvt_tf32(Q1[(r0 + qr) * 64 + c1] * 0.125f);
            qa[kb][3] = cvt_tf32(Q1[(r0 + qr + 8) * 64 + c1] * 0.125f);
        }
    }

    // store V tile 0 (tf32) + gsm 0
    #pragma unroll
    for (int p = 0; p < 8; p++) {
        int bi = warp + 4 * p;
        int key = (bi & 7) * 8 + (lane & 7);
        int d0 = ((bi >> 3) * 4 + (lane >> 3)) * 4;
        uint32_t* V = VtS[0];
        V[(d0 + 0) * 64 + (key ^ (((d0 + 0) & 7) << 3))] = cvt_tf32(vreg[p].x);
        V[(d0 + 1) * 64 + (key ^ (((d0 + 1) & 7) << 3))] = cvt_tf32(vreg[p].y);
        V[(d0 + 2) * 64 + (key ^ (((d0 + 2) & 7) << 3))] = cvt_tf32(vreg[p].z);
        V[(d0 + 3) * 64 + (key ^ (((d0 + 3) & 7) << 3))] = cvt_tf32(vreg[p].w);
    }
    if (tid < 64)
        gsmP[tid] = mnv ? __logf(fmaxf(gnv, 1e-6f)) : -1e30f;
    cp_wait_all();
    __syncthreads();

    // ================= main loop =================
    float m_a = -1e30f, m_b = -1e30f, l_a = 0.0f, l_b = 0.0f;
    float oacc[8][4];
    #pragma unroll
    for (int nb = 0; nb < 8; nb++)
        #pragma unroll
        for (int i = 0; i < 4; i++) oacc[nb][i] = 0.0f;

    #pragma unroll 1
    for (int it = 0; it < NT; it++) {
        const int cur = it & 1, nxt = cur ^ 1;
        const bool produce = (it + 1 < NT);
        const int k1 = (it + 1) * BK;

        // ---- issue next-tile loads early (latency hidden by MMA phase) ----
        if (produce) {
            #pragma unroll
            for (int p = 0; p < 8; p++) {
                int id = tid + p * 128;
                int r = id >> 4, ch = id & 15;
                cp_async16(ks_base[nxt] + r * 256 + ((ch ^ (r & 7)) << 4),
                           Kb + (size_t)(k1 + r) * DM + ch * 4);
            }
            cp_commit();
            #pragma unroll
            for (int p = 0; p < 8; p++) {
                int bi = warp + 4 * p;
                int key = (bi & 7) * 8 + (lane & 7);
                int dgrp = (bi >> 3) * 4 + (lane >> 3);
                vreg[p] = *(const float4*)(Vb + (size_t)(k1 + key) * DM + dgrp * 4);
            }
            if (tid < 64) { gnv = gb[k1 + tid]; mnv = mb[k1 + tid]; }
        }

        // ---- S = Q K^T (tf32 MMA; K cvt.rna from raw fp32) ----
        const float* KC = (const float*)KsS[cur];
        float sacc[8][4];
        #pragma unroll
        for (int nb = 0; nb < 8; nb++) {
            #pragma unroll
            for (int i = 0; i < 4; i++) sacc[nb][i] = 0.0f;
            int row = 8 * nb + qr;
            #pragma unroll
            for (int kb = 0; kb < 8; kb++) {
                uint32_t b0 = cvt_tf32(KC[row * 64 + (((2 * kb) ^ qr) * 4 + qc)]);
                uint32_t b1 = cvt_tf32(KC[row * 64 + (((2 * kb + 1) ^ qr) * 4 + qc)]);
                mma_tf32(sacc[nb], qa[kb], b0, b1);
            }
        }

        // ---- gate + mask, online softmax ----
        const float* gc = gsmP + cur * 64;
        float mxa = -1e30f, mxb = -1e30f;
        #pragma unroll
        for (int nb = 0; nb < 8; nb++) {
            float g0 = gc[8 * nb + 2 * qc];
            float g1 = gc[8 * nb + 2 * qc + 1];
            sacc[nb][0] += g0; sacc[nb][1] += g1;
            sacc[nb][2] += g0; sacc[nb][3] += g1;
            mxa = fmaxf(mxa, fmaxf(sacc[nb][0], sacc[nb][1]));
            mxb = fmaxf(mxb, fmaxf(sacc[nb][2], sacc[nb][3]));
        }
        mxa = fmaxf(mxa, __shfl_xor_sync(0xffffffffu, mxa, 1));
        mxa = fmaxf(mxa, __shfl_xor_sync(0xffffffffu, mxa, 2));
        mxb = fmaxf(mxb, __shfl_xor_sync(0xffffffffu, mxb, 1));
        mxb = fmaxf(mxb, __shfl_xor_sync(0xffffffffu, mxb, 2));

        float mna = fmaxf(m_a, mxa), mnb = fmaxf(m_b, mxb);
        float alpha_a = __expf(m_a - mna), alpha_b = __expf(m_b - mnb);
        m_a = mna; m_b = mnb;

        float suma = 0.0f, sumb = 0.0f;
        #pragma unroll
        for (int nb = 0; nb < 8; nb++) {
            sacc[nb][0] = __expf(sacc[nb][0] - m_a);
            sacc[nb][1] = __expf(sacc[nb][1] - m_a);
            sacc[nb][2] = __expf(sacc[nb][2] - m_b);
            sacc[nb][3] = __expf(sacc[nb][3] - m_b);
            suma += sacc[nb][0] + sacc[nb][1];
            sumb += sacc[nb][2] + sacc[nb][3];
        }
        suma += __shfl_xor_sync(0xffffffffu, suma, 1);
        suma += __shfl_xor_sync(0xffffffffu, suma, 2);
        sumb += __shfl_xor_sync(0xffffffffu, sumb, 1);
        sumb += __shfl_xor_sync(0xffffffffu, sumb, 2);
        l_a = l_a * alpha_a + suma;
        l_b = l_b * alpha_b + sumb;

        #pragma unroll
        for (int nb = 0; nb < 8; nb++) {
            oacc[nb][0] *= alpha_a; oacc[nb][1] *= alpha_a;
            oacc[nb][2] *= alpha_b; oacc[nb][3] *= alpha_b;
        }

        // ---- O += P V (tf32 MMA; permuted-k: A-frag = {c0,c2,c1,c3}) ----
        const uint32_t* VC = VtS[cur];
        #pragma unroll
        for (int kb = 0; kb < 8; kb++) {
            uint32_t pa[4];
            pa[0] = cvt_tf32(sacc[kb][0]);
            pa[1] = cvt_tf32(sacc[kb][2]);
            pa[2] = cvt_tf32(sacc[kb][1]);
            pa[3] = cvt_tf32(sacc[kb][3]);
            int kcol = 8 * kb + 2 * qc;
            #pragma unroll
            for (int nb = 0; nb < 8; nb++) {
                int d = 8 * nb + qr;
                uint2 bv = *(const uint2*)&VC[d * 64 + (kcol ^ (qr << 3))];
                mma_tf32(oacc[nb], pa, bv.x, bv.y);
            }
        }

        // ---- write next-tile V + gsm, close pipeline stage ----
        if (produce) {
            #pragma unroll
            for (int p = 0; p < 8; p++) {
                int bi = warp + 4 * p;
                int key = (bi & 7) * 8 + (lane & 7);
                int d0 = ((bi >> 3) * 4 + (lane >> 3)) * 4;
                uint32_t* V = VtS[nxt];
                V[(d0 + 0) * 64 + (key ^ (((d0 + 0) & 7) << 3))] = cvt_tf32(vreg[p].x);
                V[(d0 + 1) * 64 + (key ^ (((d0 + 1) & 7) << 3))] = cvt_tf32(vreg[p].y);
                V[(d0 + 2) * 64 + (key ^ (((d0 + 2) & 7) << 3))] = cvt_tf32(vreg[p].z);
                V[(d0 + 3) * 64 + (key ^ (((d0 + 3) & 7) << 3))] = cvt_tf32(vreg[p].w);
            }
            if (tid < 64)
                gsmP[nxt * 64 + tid] = mnv ? __logf(fmaxf(gnv, 1e-6f)) : -1e30f;
        }
        cp_wait_all();
        __syncthreads();
    }

    // ---- epilogue ----
    float inva = 1.0f / l_a, invb = 1.0f / l_b;
    float* Ob = g_AO + ((size_t)b * LQn + q0 + r0 + qr) * DM + h * DH;
    #pragma unroll
    for (int nb = 0; nb < 8; nb++) {
        float2 va = make_float2(oacc[nb][0] * inva, oacc[nb][1] * inva);
        *(float2*)(Ob + 8 * nb + 2 * qc) = va;
        float2 vb2 = make_float2(oacc[nb][2] * invb, oacc[nb][3] * invb);
        *(float2*)(Ob + (size_t)8 * DM + 8 * nb + 2 * qc) = vb2;
    }
}

extern "C" void kernel_launch(void* const* d_in, const int* in_sizes, int n_in,
                              void* d_out, int out_size) {
    const float* q    = (const float*)d_in[0];
    const float* kv   = (const float*)d_in[1];
    const float* gate = (const float*)d_in[2];
    const int*   mask = (const int*)d_in[3];
    const float* Wq   = (const float*)d_in[4];
    const float* bq   = (const float*)d_in[5];
    const float* Wk   = (const float*)d_in[6];
    const float* bk   = (const float*)d_in[7];
    const float* Wv   = (const float*)d_in[8];
    const float* bv   = (const float*)d_in[9];
    const float* Wo   = (const float*)d_in[10];
    const float* bo   = (const float*)d_in[11];
    float* out = (float*)d_out;

    float *Qp, *Kp, *Vp, *AO;
    cudaGetSymbolAddress((void**)&Qp, g_Qp);
    cudaGetSymbolAddress((void**)&Kp, g_Kp);
    cudaGetSymbolAddress((void**)&Vp, g_Vp);
    cudaGetSymbolAddress((void**)&AO, g_AO);

    cudaFuncSetAttribute(attn_kernel,
                         cudaFuncAttributeMaxDynamicSharedMemorySize, ATTN_SMEM);

    // Projections (tensor-core bf16-split GEMMs, 128x64 tiles)
    gemm_bf16_kernel<<<dim3(DM / 64, (BSZ * LQn) / 128), 256>>>(q,  Wq, bq, Qp, BSZ * LQn);
    gemm_bf16_kernel<<<dim3(DM / 64, (BSZ * LKn) / 128), 256>>>(kv, Wk, bk, Kp, BSZ * LKn);
    gemm_bf16_kernel<<<dim3(DM / 64, (BSZ * LKn) / 128), 256>>>(kv, Wv, bv, Vp, BSZ * LKn);
    // Attention (tf32 tensor cores, pipelined)
    attn_kernel<<<dim3(LQn / BQ, NH, BSZ), 128, ATTN_SMEM>>>(gate, mask);
    // Output projection
    gemm_bf16_kernel<<<dim3(DM / 64, (BSZ * LQn) / 128), 256>>>(AO, Wo, bo, out, BSZ * LQn);
}

// round 15
// speedup vs baseline: 1.4155x; 1.4155x over previous
#include <cuda_runtime.h>
#include <cuda_bf16.h>
#include <math.h>
#include <stdint.h>

#define DM 512
#define NH 8
#define DH 64
#define LQn 2048
#define LKn 4096
#define BSZ 2

#define BQ 128
#define BK 64
#define NT (LKn / BK)

// Scratch (allocation-free): projected Q/K/V and attention output, all fp32.
__device__ float g_Qp[(size_t)BSZ * LQn * DM];
__device__ float g_Kp[(size_t)BSZ * LKn * DM];
__device__ float g_Vp[(size_t)BSZ * LKn * DM];
__device__ float g_AO[(size_t)BSZ * LQn * DM];

// ---------------------------------------------------------------------------
// MMA + packing primitives
// ---------------------------------------------------------------------------
__device__ __forceinline__ void mma_tf32(float c[4], const uint32_t a[4],
                                         uint32_t b0, uint32_t b1) {
    asm volatile(
        "mma.sync.aligned.m16n8k8.row.col.f32.tf32.tf32.f32 "
        "{%0,%1,%2,%3}, {%4,%5,%6,%7}, {%8,%9}, {%0,%1,%2,%3};"
        : "+f"(c[0]), "+f"(c[1]), "+f"(c[2]), "+f"(c[3])
        : "r"(a[0]), "r"(a[1]), "r"(a[2]), "r"(a[3]), "r"(b0), "r"(b1));
}

__device__ __forceinline__ void mma_bf16(float c[4], const uint32_t a[4],
                                         uint32_t b0, uint32_t b1) {
    asm volatile(
        "mma.sync.aligned.m16n8k16.row.col.f32.bf16.bf16.f32 "
        "{%0,%1,%2,%3}, {%4,%5,%6,%7}, {%8,%9}, {%0,%1,%2,%3};"
        : "+f"(c[0]), "+f"(c[1]), "+f"(c[2]), "+f"(c[3])
        : "r"(a[0]), "r"(a[1]), "r"(a[2]), "r"(a[3]), "r"(b0), "r"(b1));
}

__device__ __forceinline__ uint32_t cvt_tf32(float f) {
    uint32_t u;
    asm("cvt.rna.tf32.f32 %0, %1;" : "=r"(u) : "f"(f));
    return u;
}

__device__ __forceinline__ float ex2f(float x) {
    float r;
    asm("ex2.approx.ftz.f32 %0, %1;" : "=f"(r) : "f"(x));
    return r;
}

__device__ __forceinline__ void pack_bf16_hilo(float f0, float f1,
                                               uint32_t& hi, uint32_t& lo) {
    asm("cvt.rn.bf16x2.f32 %0, %1, %2;" : "=r"(hi) : "f"(f1), "f"(f0));
    float h0 = __uint_as_float(hi << 16);
    float h1 = __uint_as_float(hi & 0xffff0000u);
    float r0 = f0 - h0, r1 = f1 - h1;
    asm("cvt.rn.bf16x2.f32 %0, %1, %2;" : "=r"(lo) : "f"(r1), "f"(r0));
}

// ---------------------------------------------------------------------------
// Tensor-core GEMM: C[M,512] = A[M,512] @ W[512,512]^T + bias
// bf16 3-term hi/lo split. CTA: 128 threads / 4 warps; tile 64x64.
// (identical to the measured-151us round-5 version)
// ---------------------------------------------------------------------------
#define GS 20   // uint32 stride of packed-k rows (16 used + 4 pad)

__global__ __launch_bounds__(128)
void gemm_bf16_kernel(const float* __restrict__ A,
                      const float* __restrict__ W,
                      const float* __restrict__ bias,
                      float* __restrict__ C, int M) {
    __shared__ uint32_t AsH[64 * GS], AsL[64 * GS];
    __shared__ uint32_t WsH[64 * GS], WsL[64 * GS];

    const int tid = threadIdx.x;
    const int lane = tid & 31, warp = tid >> 5;
    const int qr = lane >> 2, qc = lane & 3;
    const int n0 = blockIdx.x * 64, m0 = blockIdx.y * 64;

    float acc[8][4];
    #pragma unroll
    for (int nb = 0; nb < 8; nb++)
        #pragma unroll
        for (int i = 0; i < 4; i++) acc[nb][i] = 0.0f;

    for (int k0 = 0; k0 < DM; k0 += 32) {
        __syncthreads();
        #pragma unroll
        for (int p = 0; p < 4; p++) {
            int idx = tid + p * 128;
            int r = idx >> 3, fg = idx & 7;
            float4 av = *(const float4*)(A + (size_t)(m0 + r) * DM + k0 + fg * 4);
            uint32_t h0, l0, h1, l1;
            pack_bf16_hilo(av.x, av.y, h0, l0);
            pack_bf16_hilo(av.z, av.w, h1, l1);
            AsH[r * GS + fg * 2] = h0; AsH[r * GS + fg * 2 + 1] = h1;
            AsL[r * GS + fg * 2] = l0; AsL[r * GS + fg * 2 + 1] = l1;
            float4 wv = *(const float4*)(W + (size_t)(n0 + r) * DM + k0 + fg * 4);
            pack_bf16_hilo(wv.x, wv.y, h0, l0);
            pack_bf16_hilo(wv.z, wv.w, h1, l1);
            WsH[r * GS + fg * 2] = h0; WsH[r * GS + fg * 2 + 1] = h1;
            WsL[r * GS + fg * 2] = l0; WsL[r * GS + fg * 2 + 1] = l1;
        }
        __syncthreads();

        uint32_t ahH[2][4], ahL[2][4];
        #pragma unroll
        for (int kb = 0; kb < 2; kb++) {
            int base = (16 * warp + qr) * GS + kb * 8 + qc;
            ahH[kb][0] = AsH[base];     ahH[kb][1] = AsH[base + 8 * GS];
            ahH[kb][2] = AsH[base + 4]; ahH[kb][3] = AsH[base + 8 * GS + 4];
            ahL[kb][0] = AsL[base];     ahL[kb][1] = AsL[base + 8 * GS];
            ahL[kb][2] = AsL[base + 4]; ahL[kb][3] = AsL[base + 8 * GS + 4];
        }

        #pragma unroll
        for (int nb = 0; nb < 8; nb++) {
            #pragma unroll
            for (int kb = 0; kb < 2; kb++) {
                int wb = (8 * nb + qr) * GS + kb * 8 + qc;
                uint32_t bh0 = WsH[wb], bh1 = WsH[wb + 4];
                uint32_t bl0 = WsL[wb], bl1 = WsL[wb + 4];
                mma_bf16(acc[nb], ahH[kb], bh0, bh1);
                mma_bf16(acc[nb], ahL[kb], bh0, bh1);
                mma_bf16(acc[nb], ahH[kb], bl0, bl1);
            }
        }
    }

    const int row0 = m0 + 16 * warp + qr;
    #pragma unroll
    for (int nb = 0; nb < 8; nb++) {
        int n = n0 + 8 * nb + 2 * qc;
        float2 bv = *(const float2*)(bias + n);
        float2 c01 = make_float2(acc[nb][0] + bv.x, acc[nb][1] + bv.y);
        float2 c23 = make_float2(acc[nb][2] + bv.x, acc[nb][3] + bv.y);
        *(float2*)(C + (size_t)row0 * DM + n) = c01;
        *(float2*)(C + (size_t)(row0 + 8) * DM + n) = c23;
    }
}

// ---------------------------------------------------------------------------
// Tensor-core flash attention. BQ=128 (8 warps x 16 q-rows), BK=64.
//   S = Q K^T : tf32 MMA, K pre-converted in smem (stride 68, conflict-free).
//   P V      : tf32 MMA, permuted-k (A-frag = {c0,c2,c1,c3} register-only;
//              B-frag = adjacent key pair LDS.64 from V^T stride 72,
//              bank = 4qr+qc+4kb = lane-distinct -> conflict-free).
//   Softmax in base-2 domain (log2e folded into Q scale and gate log).
// Static smem: Ks 64*68*4 + Vt 64*72*4 + gsm = ~35.3 KB.
// ---------------------------------------------------------------------------
#define KS 68   // uint32 stride, K rows
#define VS 72   // uint32 stride, V^T rows

__global__ __launch_bounds__(256, 1)
void attn_kernel(const float* __restrict__ gate, const int* __restrict__ mask) {
    __shared__ uint32_t Ks[BK * KS];
    __shared__ uint32_t Vt[DH * VS];
    __shared__ float gsm[BK];

    const int tid = threadIdx.x;
    const int lane = tid & 31, warp = tid >> 5;
    const int qr = lane >> 2;       // 0..7
    const int qc = lane & 3;        // 0..3
    const int r0 = warp * 16;       // warp's q-row base (8 warps x 16 = 128)

    const int q0 = blockIdx.x * BQ;
    const int h = blockIdx.y, b = blockIdx.z;

    const float* Qb = g_Qp + ((size_t)b * LQn + q0) * DM + h * DH;
    const float* Kb = g_Kp + (size_t)b * LKn * DM + h * DH;
    const float* Vb = g_Vp + (size_t)b * LKn * DM + h * DH;
    const float* gb = gate + (size_t)b * LKn;
    const int*   mb = mask + (size_t)b * LKn;

    // ---- Q A-fragments straight from gmem (one-time), scale*log2e folded ----
    const float QSC = 0.125f * 1.44269504088896f;
    uint32_t qa[8][4];
    {
        const float* Qr0 = Qb + (size_t)(r0 + qr) * DM;
        const float* Qr1 = Qb + (size_t)(r0 + qr + 8) * DM;
        #pragma unroll
        for (int kb = 0; kb < 8; kb++) {
            qa[kb][0] = cvt_tf32(Qr0[8 * kb + qc] * QSC);
            qa[kb][1] = cvt_tf32(Qr1[8 * kb + qc] * QSC);
            qa[kb][2] = cvt_tf32(Qr0[8 * kb + qc + 4] * QSC);
            qa[kb][3] = cvt_tf32(Qr1[8 * kb + qc + 4] * QSC);
        }
    }

    float m_a = -1e30f, m_b = -1e30f, l_a = 0.0f, l_b = 0.0f;
    float oacc[8][4];
    #pragma unroll
    for (int nb = 0; nb < 8; nb++)
        #pragma unroll
        for (int i = 0; i < 4; i++) oacc[nb][i] = 0.0f;

    #pragma unroll 1
    for (int it = 0; it < NT; it++) {
        const int k0 = it * BK;

        // ---- K tile -> tf32 smem (coalesced LDG.128, STS.128) ----
        #pragma unroll
        for (int p = 0; p < 4; p++) {
            int idx = tid + p * 256;
            int r = idx >> 4, cg = (idx & 15) << 2;
            float4 v = *(const float4*)(Kb + (size_t)(k0 + r) * DM + cg);
            uint4 u;
            u.x = cvt_tf32(v.x); u.y = cvt_tf32(v.y);
            u.z = cvt_tf32(v.z); u.w = cvt_tf32(v.w);
            *(uint4*)&Ks[r * KS + cg] = u;
        }
        // ---- V tile -> tf32 V^T smem (key-spread, conflict-free STS) ----
        #pragma unroll
        for (int p = 0; p < 4; p++) {
            int idx = tid + p * 256;
            int key = idx & 63, dgrp = idx >> 6;   // key lane-distinct mod 32
            float4 v = *(const float4*)(Vb + (size_t)(k0 + key) * DM + dgrp * 4);
            int d0 = dgrp * 4;
            Vt[(d0 + 0) * VS + key] = cvt_tf32(v.x);
            Vt[(d0 + 1) * VS + key] = cvt_tf32(v.y);
            Vt[(d0 + 2) * VS + key] = cvt_tf32(v.z);
            Vt[(d0 + 3) * VS + key] = cvt_tf32(v.w);
        }
        // ---- gate/mask additive terms (base-2) ----
        if (tid < BK) {
            float g = __log2f(fmaxf(gb[k0 + tid], 1e-6f));
            gsm[tid] = (mb[k0 + tid] == 0) ? -1e30f : g;
        }
        __syncthreads();

        // ---- S = Q K^T (tf32 MMA) ----
        float sacc[8][4];
        #pragma unroll
        for (int nb = 0; nb < 8; nb++) {
            #pragma unroll
            for (int i = 0; i < 4; i++) sacc[nb][i] = 0.0f;
            int row = 8 * nb + qr;
            #pragma unroll
            for (int kb = 0; kb < 8; kb++) {
                uint32_t b0 = Ks[row * KS + 8 * kb + qc];
                uint32_t b1 = Ks[row * KS + 8 * kb + qc + 4];
                mma_tf32(sacc[nb], qa[kb], b0, b1);
            }
        }

        // ---- gate + mask, online softmax (base-2) ----
        float mxa = -1e30f, mxb = -1e30f;
        #pragma unroll
        for (int nb = 0; nb < 8; nb++) {
            float g0 = gsm[8 * nb + 2 * qc];
            float g1 = gsm[8 * nb + 2 * qc + 1];
            sacc[nb][0] += g0; sacc[nb][1] += g1;
            sacc[nb][2] += g0; sacc[nb][3] += g1;
            mxa = fmaxf(mxa, fmaxf(sacc[nb][0], sacc[nb][1]));
            mxb = fmaxf(mxb, fmaxf(sacc[nb][2], sacc[nb][3]));
        }
        mxa = fmaxf(mxa, __shfl_xor_sync(0xffffffffu, mxa, 1));
        mxa = fmaxf(mxa, __shfl_xor_sync(0xffffffffu, mxa, 2));
        mxb = fmaxf(mxb, __shfl_xor_sync(0xffffffffu, mxb, 1));
        mxb = fmaxf(mxb, __shfl_xor_sync(0xffffffffu, mxb, 2));

        float mna = fmaxf(m_a, mxa), mnb = fmaxf(m_b, mxb);
        float alpha_a = ex2f(m_a - mna), alpha_b = ex2f(m_b - mnb);
        m_a = mna; m_b = mnb;

        float suma = 0.0f, sumb = 0.0f;
        #pragma unroll
        for (int nb = 0; nb < 8; nb++) {
            sacc[nb][0] = ex2f(sacc[nb][0] - m_a);
            sacc[nb][1] = ex2f(sacc[nb][1] - m_a);
            sacc[nb][2] = ex2f(sacc[nb][2] - m_b);
            sacc[nb][3] = ex2f(sacc[nb][3] - m_b);
            suma += sacc[nb][0] + sacc[nb][1];
            sumb += sacc[nb][2] + sacc[nb][3];
        }
        suma += __shfl_xor_sync(0xffffffffu, suma, 1);
        suma += __shfl_xor_sync(0xffffffffu, suma, 2);
        sumb += __shfl_xor_sync(0xffffffffu, sumb, 1);
        sumb += __shfl_xor_sync(0xffffffffu, sumb, 2);
        l_a = l_a * alpha_a + suma;
        l_b = l_b * alpha_b + sumb;

        #pragma unroll
        for (int nb = 0; nb < 8; nb++) {
            oacc[nb][0] *= alpha_a; oacc[nb][1] *= alpha_a;
            oacc[nb][2] *= alpha_b; oacc[nb][3] *= alpha_b;
        }

        // ---- O += P V (tf32 MMA, permuted-k; B = adjacent key pair LDS.64) ----
        #pragma unroll
        for (int kb = 0; kb < 8; kb++) {
            uint32_t pa[4];
            pa[0] = cvt_tf32(sacc[kb][0]);
            pa[1] = cvt_tf32(sacc[kb][2]);
            pa[2] = cvt_tf32(sacc[kb][1]);
            pa[3] = cvt_tf32(sacc[kb][3]);
            int kcol = 8 * kb + 2 * qc;
            #pragma unroll
            for (int nb = 0; nb < 8; nb++) {
                int d = 8 * nb + qr;
                uint2 bv = *(const uint2*)&Vt[d * VS + kcol];
                mma_tf32(oacc[nb], pa, bv.x, bv.y);
            }
        }
        __syncthreads();
    }

    // ---- epilogue ----
    float inva = 1.0f / l_a, invb = 1.0f / l_b;
    float* Ob = g_AO + ((size_t)b * LQn + q0 + r0 + qr) * DM + h * DH;
    #pragma unroll
    for (int nb = 0; nb < 8; nb++) {
        float2 va = make_float2(oacc[nb][0] * inva, oacc[nb][1] * inva);
        *(float2*)(Ob + 8 * nb + 2 * qc) = va;
        float2 vb2 = make_float2(oacc[nb][2] * invb, oacc[nb][3] * invb);
        *(float2*)(Ob + (size_t)8 * DM + 8 * nb + 2 * qc) = vb2;
    }
}

extern "C" void kernel_launch(void* const* d_in, const int* in_sizes, int n_in,
                              void* d_out, int out_size) {
    const float* q    = (const float*)d_in[0];
    const float* kv   = (const float*)d_in[1];
    const float* gate = (const float*)d_in[2];
    const int*   mask = (const int*)d_in[3];
    const float* Wq   = (const float*)d_in[4];
    const float* bq   = (const float*)d_in[5];
    const float* Wk   = (const float*)d_in[6];
    const float* bk   = (const float*)d_in[7];
    const float* Wv   = (const float*)d_in[8];
    const float* bv   = (const float*)d_in[9];
    const float* Wo   = (const float*)d_in[10];
    const float* bo   = (const float*)d_in[11];
    float* out = (float*)d_out;

    float *Qp, *Kp, *Vp, *AO;
    cudaGetSymbolAddress((void**)&Qp, g_Qp);
    cudaGetSymbolAddress((void**)&Kp, g_Kp);
    cudaGetSymbolAddress((void**)&Vp, g_Vp);
    cudaGetSymbolAddress((void**)&AO, g_AO);

    // Projections (tensor-core bf16-split GEMMs, 64x64 tiles)
    gemm_bf16_kernel<<<dim3(DM / 64, (BSZ * LQn) / 64), 128>>>(q,  Wq, bq, Qp, BSZ * LQn);
    gemm_bf16_kernel<<<dim3(DM / 64, (BSZ * LKn) / 64), 128>>>(kv, Wk, bk, Kp, BSZ * LKn);
    gemm_bf16_kernel<<<dim3(DM / 64, (BSZ * LKn) / 64), 128>>>(kv, Wv, bv, Vp, BSZ * LKn);
    // Attention (tf32 tensor cores, BQ=128)
    attn_kernel<<<dim3(LQn / BQ, NH, BSZ), 256>>>(gate, mask);
    // Output projection
    gemm_bf16_kernel<<<dim3(DM / 64, (BSZ * LQn) / 64), 128>>>(AO, Wo, bo, out, BSZ * LQn);
}

// round 16
// speedup vs baseline: 1.4859x; 1.0498x over previous
#include <cuda_runtime.h>
#include <cuda_bf16.h>
#include <math.h>
#include <stdint.h>

#define DM 512
#define NH 8
#define DH 64
#define LQn 2048
#define LKn 4096
#define BSZ 2

#define BQ 128
#define BK 64
#define NT (LKn / BK)

// Scratch (allocation-free): projected Q/K/V and attention output, all fp32.
__device__ float g_Qp[(size_t)BSZ * LQn * DM];
__device__ float g_Kp[(size_t)BSZ * LKn * DM];
__device__ float g_Vp[(size_t)BSZ * LKn * DM];
__device__ float g_AO[(size_t)BSZ * LQn * DM];

// ---------------------------------------------------------------------------
// MMA + packing primitives
// ---------------------------------------------------------------------------
__device__ __forceinline__ void mma_tf32(float c[4], const uint32_t a[4],
                                         uint32_t b0, uint32_t b1) {
    asm volatile(
        "mma.sync.aligned.m16n8k8.row.col.f32.tf32.tf32.f32 "
        "{%0,%1,%2,%3}, {%4,%5,%6,%7}, {%8,%9}, {%0,%1,%2,%3};"
        : "+f"(c[0]), "+f"(c[1]), "+f"(c[2]), "+f"(c[3])
        : "r"(a[0]), "r"(a[1]), "r"(a[2]), "r"(a[3]), "r"(b0), "r"(b1));
}

__device__ __forceinline__ void mma_bf16(float c[4], const uint32_t a[4],
                                         uint32_t b0, uint32_t b1) {
    asm volatile(
        "mma.sync.aligned.m16n8k16.row.col.f32.bf16.bf16.f32 "
        "{%0,%1,%2,%3}, {%4,%5,%6,%7}, {%8,%9}, {%0,%1,%2,%3};"
        : "+f"(c[0]), "+f"(c[1]), "+f"(c[2]), "+f"(c[3])
        : "r"(a[0]), "r"(a[1]), "r"(a[2]), "r"(a[3]), "r"(b0), "r"(b1));
}

__device__ __forceinline__ uint32_t cvt_tf32(float f) {
    uint32_t u;
    asm("cvt.rna.tf32.f32 %0, %1;" : "=r"(u) : "f"(f));
    return u;
}

__device__ __forceinline__ float ex2f(float x) {
    float r;
    asm("ex2.approx.ftz.f32 %0, %1;" : "=f"(r) : "f"(x));
    return r;
}

__device__ __forceinline__ void pack_bf16_hilo(float f0, float f1,
                                               uint32_t& hi, uint32_t& lo) {
    asm("cvt.rn.bf16x2.f32 %0, %1, %2;" : "=r"(hi) : "f"(f1), "f"(f0));
    float h0 = __uint_as_float(hi << 16);
    float h1 = __uint_as_float(hi & 0xffff0000u);
    float r0 = f0 - h0, r1 = f1 - h1;
    asm("cvt.rn.bf16x2.f32 %0, %1, %2;" : "=r"(lo) : "f"(r1), "f"(r0));
}

// ---------------------------------------------------------------------------
// Tensor-core GEMM: C[M,512] = A[M,512] @ W[512,512]^T + bias
// bf16 3-term hi/lo split. CTA: 128 threads / 4 warps; tile 64x64.
// (unchanged — measured ~142-151us for all four)
// ---------------------------------------------------------------------------
#define GS 20   // uint32 stride of packed-k rows (16 used + 4 pad)

__global__ __launch_bounds__(128)
void gemm_bf16_kernel(const float* __restrict__ A,
                      const float* __restrict__ W,
                      const float* __restrict__ bias,
                      float* __restrict__ C, int M) {
    __shared__ uint32_t AsH[64 * GS], AsL[64 * GS];
    __shared__ uint32_t WsH[64 * GS], WsL[64 * GS];

    const int tid = threadIdx.x;
    const int lane = tid & 31, warp = tid >> 5;
    const int qr = lane >> 2, qc = lane & 3;
    const int n0 = blockIdx.x * 64, m0 = blockIdx.y * 64;

    float acc[8][4];
    #pragma unroll
    for (int nb = 0; nb < 8; nb++)
        #pragma unroll
        for (int i = 0; i < 4; i++) acc[nb][i] = 0.0f;

    for (int k0 = 0; k0 < DM; k0 += 32) {
        __syncthreads();
        #pragma unroll
        for (int p = 0; p < 4; p++) {
            int idx = tid + p * 128;
            int r = idx >> 3, fg = idx & 7;
            float4 av = *(const float4*)(A + (size_t)(m0 + r) * DM + k0 + fg * 4);
            uint32_t h0, l0, h1, l1;
            pack_bf16_hilo(av.x, av.y, h0, l0);
            pack_bf16_hilo(av.z, av.w, h1, l1);
            AsH[r * GS + fg * 2] = h0; AsH[r * GS + fg * 2 + 1] = h1;
            AsL[r * GS + fg * 2] = l0; AsL[r * GS + fg * 2 + 1] = l1;
            float4 wv = *(const float4*)(W + (size_t)(n0 + r) * DM + k0 + fg * 4);
            pack_bf16_hilo(wv.x, wv.y, h0, l0);
            pack_bf16_hilo(wv.z, wv.w, h1, l1);
            WsH[r * GS + fg * 2] = h0; WsH[r * GS + fg * 2 + 1] = h1;
            WsL[r * GS + fg * 2] = l0; WsL[r * GS + fg * 2 + 1] = l1;
        }
        __syncthreads();

        uint32_t ahH[2][4], ahL[2][4];
        #pragma unroll
        for (int kb = 0; kb < 2; kb++) {
            int base = (16 * warp + qr) * GS + kb * 8 + qc;
            ahH[kb][0] = AsH[base];     ahH[kb][1] = AsH[base + 8 * GS];
            ahH[kb][2] = AsH[base + 4]; ahH[kb][3] = AsH[base + 8 * GS + 4];
            ahL[kb][0] = AsL[base];     ahL[kb][1] = AsL[base + 8 * GS];
            ahL[kb][2] = AsL[base + 4]; ahL[kb][3] = AsL[base + 8 * GS + 4];
        }

        #pragma unroll
        for (int nb = 0; nb < 8; nb++) {
            #pragma unroll
            for (int kb = 0; kb < 2; kb++) {
                int wb = (8 * nb + qr) * GS + kb * 8 + qc;
                uint32_t bh0 = WsH[wb], bh1 = WsH[wb + 4];
                uint32_t bl0 = WsL[wb], bl1 = WsL[wb + 4];
                mma_bf16(acc[nb], ahH[kb], bh0, bh1);
                mma_bf16(acc[nb], ahL[kb], bh0, bh1);
                mma_bf16(acc[nb], ahH[kb], bl0, bl1);
            }
        }
    }

    const int row0 = m0 + 16 * warp + qr;
    #pragma unroll
    for (int nb = 0; nb < 8; nb++) {
        int n = n0 + 8 * nb + 2 * qc;
        float2 bv = *(const float2*)(bias + n);
        float2 c01 = make_float2(acc[nb][0] + bv.x, acc[nb][1] + bv.y);
        float2 c23 = make_float2(acc[nb][2] + bv.x, acc[nb][3] + bv.y);
        *(float2*)(C + (size_t)row0 * DM + n) = c01;
        *(float2*)(C + (size_t)(row0 + 8) * DM + n) = c23;
    }
}

// ---------------------------------------------------------------------------
// Tensor-core flash attention. BQ=128 (8 warps x 16 q-rows), BK=64.
// Occupancy-2 variant: Q A-fragments live in a per-warp smem buffer in exact
// fragment order (LDS.128 to restore 4 regs), S-loop kb-outer so only 4 qa
// regs are live -> fits 128 regs -> 2 CTAs/SM (512 thr/SM), single wave.
//   S  = Q K^T : tf32 MMA, K tf32 smem stride 68 (conflict-free).
//   PV = P V   : tf32 MMA permuted-k, V^T stride 72, LDS.64 (conflict-free).
//   Softmax base-2 (log2e folded into Q scale and gate log).
// Dynamic smem: Qf 32KB + Ks 17KB + Vt 18KB + gsm 256B = 67.25 KB.
// ---------------------------------------------------------------------------
#define KS 68   // uint32 stride, K rows
#define VS 72   // uint32 stride, V^T rows
#define QF_OFF   0
#define KS_OFF   8192
#define VT_OFF   (8192 + 4352)
#define GSM_OFF  (8192 + 4352 + 4608)
#define ATTN_SMEM ((8192 + 4352 + 4608 + 64) * 4)

__global__ __launch_bounds__(256, 2)
void attn_kernel(const float* __restrict__ gate, const int* __restrict__ mask) {
    extern __shared__ uint32_t smdyn[];
    uint32_t* Qf = smdyn + QF_OFF;       // [warp][kb][lane][4] fragment order
    uint32_t* Ks = smdyn + KS_OFF;
    uint32_t* Vt = smdyn + VT_OFF;
    float*   gsm = (float*)(smdyn + GSM_OFF);

    const int tid = threadIdx.x;
    const int lane = tid & 31, warp = tid >> 5;
    const int qr = lane >> 2;       // 0..7
    const int qc = lane & 3;        // 0..3
    const int r0 = warp * 16;       // warp's q-row base (8 warps x 16 = 128)

    const int q0 = blockIdx.x * BQ;
    const int h = blockIdx.y, b = blockIdx.z;

    const float* Qb = g_Qp + ((size_t)b * LQn + q0) * DM + h * DH;
    const float* Kb = g_Kp + (size_t)b * LKn * DM + h * DH;
    const float* Vb = g_Vp + (size_t)b * LKn * DM + h * DH;
    const float* gb = gate + (size_t)b * LKn;
    const int*   mb = mask + (size_t)b * LKn;

    // ---- One-time: Q A-fragments (scale*log2e folded) -> smem frag buffer.
    // Each thread writes and later reads ONLY its own slot: no barrier needed.
    {
        const float QSC = 0.125f * 1.44269504088896f;
        const float* Qr0 = Qb + (size_t)(r0 + qr) * DM;
        const float* Qr1 = Qb + (size_t)(r0 + qr + 8) * DM;
        #pragma unroll
        for (int kb = 0; kb < 8; kb++) {
            uint4 u;
            u.x = cvt_tf32(Qr0[8 * kb + qc] * QSC);
            u.y = cvt_tf32(Qr1[8 * kb + qc] * QSC);
            u.z = cvt_tf32(Qr0[8 * kb + qc + 4] * QSC);
            u.w = cvt_tf32(Qr1[8 * kb + qc + 4] * QSC);
            *(uint4*)&Qf[((warp * 8 + kb) * 32 + lane) * 4] = u;
        }
    }

    float m_a = -1e30f, m_b = -1e30f, l_a = 0.0f, l_b = 0.0f;
    float oacc[8][4];
    #pragma unroll
    for (int nb = 0; nb < 8; nb++)
        #pragma unroll
        for (int i = 0; i < 4; i++) oacc[nb][i] = 0.0f;

    #pragma unroll 1
    for (int it = 0; it < NT; it++) {
        const int k0 = it * BK;

        // ---- K tile -> tf32 smem (coalesced LDG.128, STS.128) ----
        #pragma unroll
        for (int p = 0; p < 4; p++) {
            int idx = tid + p * 256;
            int r = idx >> 4, cg = (idx & 15) << 2;
            float4 v = *(const float4*)(Kb + (size_t)(k0 + r) * DM + cg);
            uint4 u;
            u.x = cvt_tf32(v.x); u.y = cvt_tf32(v.y);
            u.z = cvt_tf32(v.z); u.w = cvt_tf32(v.w);
            *(uint4*)&Ks[r * KS + cg] = u;
        }
        // ---- V tile -> tf32 V^T smem (key-spread, conflict-free STS) ----
        #pragma unroll
        for (int p = 0; p < 4; p++) {
            int idx = tid + p * 256;
            int key = idx & 63, dgrp = idx >> 6;   // key lane-distinct mod 32
            float4 v = *(const float4*)(Vb + (size_t)(k0 + key) * DM + dgrp * 4);
            int d0 = dgrp * 4;
            Vt[(d0 + 0) * VS + key] = cvt_tf32(v.x);
            Vt[(d0 + 1) * VS + key] = cvt_tf32(v.y);
            Vt[(d0 + 2) * VS + key] = cvt_tf32(v.z);
            Vt[(d0 + 3) * VS + key] = cvt_tf32(v.w);
        }
        // ---- gate/mask additive terms (base-2) ----
        if (tid < BK) {
            float g = __log2f(fmaxf(gb[k0 + tid], 1e-6f));
            gsm[tid] = (mb[k0 + tid] == 0) ? -1e30f : g;
        }
        __syncthreads();

        // ---- S = Q K^T (tf32 MMA; kb-outer, qa streamed from smem) ----
        float sacc[8][4];
        #pragma unroll
        for (int nb = 0; nb < 8; nb++)
            #pragma unroll
            for (int i = 0; i < 4; i++) sacc[nb][i] = 0.0f;
        #pragma unroll
        for (int kb = 0; kb < 8; kb++) {
            uint4 q4 = *(const uint4*)&Qf[((warp * 8 + kb) * 32 + lane) * 4];
            uint32_t qa[4] = { q4.x, q4.y, q4.z, q4.w };
            #pragma unroll
            for (int nb = 0; nb < 8; nb++) {
                int row = 8 * nb + qr;
                uint32_t b0 = Ks[row * KS + 8 * kb + qc];
                uint32_t b1 = Ks[row * KS + 8 * kb + qc + 4];
                mma_tf32(sacc[nb], qa, b0, b1);
            }
        }

        // ---- gate + mask, online softmax (base-2) ----
        float mxa = -1e30f, mxb = -1e30f;
        #pragma unroll
        for (int nb = 0; nb < 8; nb++) {
            float g0 = gsm[8 * nb + 2 * qc];
            float g1 = gsm[8 * nb + 2 * qc + 1];
            sacc[nb][0] += g0; sacc[nb][1] += g1;
            sacc[nb][2] += g0; sacc[nb][3] += g1;
            mxa = fmaxf(mxa, fmaxf(sacc[nb][0], sacc[nb][1]));
            mxb = fmaxf(mxb, fmaxf(sacc[nb][2], sacc[nb][3]));
        }
        mxa = fmaxf(mxa, __shfl_xor_sync(0xffffffffu, mxa, 1));
        mxa = fmaxf(mxa, __shfl_xor_sync(0xffffffffu, mxa, 2));
        mxb = fmaxf(mxb, __shfl_xor_sync(0xffffffffu, mxb, 1));
        mxb = fmaxf(mxb, __shfl_xor_sync(0xffffffffu, mxb, 2));

        float mna = fmaxf(m_a, mxa), mnb = fmaxf(m_b, mxb);
        float alpha_a = ex2f(m_a - mna), alpha_b = ex2f(m_b - mnb);
        m_a = mna; m_b = mnb;

        float suma = 0.0f, sumb = 0.0f;
        #pragma unroll
        for (int nb = 0; nb < 8; nb++) {
            sacc[nb][0] = ex2f(sacc[nb][0] - m_a);
            sacc[nb][1] = ex2f(sacc[nb][1] - m_a);
            sacc[nb][2] = ex2f(sacc[nb][2] - m_b);
            sacc[nb][3] = ex2f(sacc[nb][3] - m_b);
            suma += sacc[nb][0] + sacc[nb][1];
            sumb += sacc[nb][2] + sacc[nb][3];
        }
        suma += __shfl_xor_sync(0xffffffffu, suma, 1);
        suma += __shfl_xor_sync(0xffffffffu, suma, 2);
        sumb += __shfl_xor_sync(0xffffffffu, sumb, 1);
        sumb += __shfl_xor_sync(0xffffffffu, sumb, 2);
        l_a = l_a * alpha_a + suma;
        l_b = l_b * alpha_b + sumb;

        #pragma unroll
        for (int nb = 0; nb < 8; nb++) {
            oacc[nb][0] *= alpha_a; oacc[nb][1] *= alpha_a;
            oacc[nb][2] *= alpha_b; oacc[nb][3] *= alpha_b;
        }

        // ---- O += P V (tf32 MMA, permuted-k; B = adjacent key pair LDS.64) ----
        #pragma unroll
        for (int kb = 0; kb < 8; kb++) {
            uint32_t pa[4];
            pa[0] = cvt_tf32(sacc[kb][0]);
            pa[1] = cvt_tf32(sacc[kb][2]);
            pa[2] = cvt_tf32(sacc[kb][1]);
            pa[3] = cvt_tf32(sacc[kb][3]);
            int kcol = 8 * kb + 2 * qc;
            #pragma unroll
            for (int nb = 0; nb < 8; nb++) {
                int d = 8 * nb + qr;
                uint2 bv = *(const uint2*)&Vt[d * VS + kcol];
                mma_tf32(oacc[nb], pa, bv.x, bv.y);
            }
        }
        __syncthreads();
    }

    // ---- epilogue ----
    float inva = 1.0f / l_a, invb = 1.0f / l_b;
    float* Ob = g_AO + ((size_t)b * LQn + q0 + r0 + qr) * DM + h * DH;
    #pragma unroll
    for (int nb = 0; nb < 8; nb++) {
        float2 va = make_float2(oacc[nb][0] * inva, oacc[nb][1] * inva);
        *(float2*)(Ob + 8 * nb + 2 * qc) = va;
        float2 vb2 = make_float2(oacc[nb][2] * invb, oacc[nb][3] * invb);
        *(float2*)(Ob + (size_t)8 * DM + 8 * nb + 2 * qc) = vb2;
    }
}

extern "C" void kernel_launch(void* const* d_in, const int* in_sizes, int n_in,
                              void* d_out, int out_size) {
    const float* q    = (const float*)d_in[0];
    const float* kv   = (const float*)d_in[1];
    const float* gate = (const float*)d_in[2];
    const int*   mask = (const int*)d_in[3];
    const float* Wq   = (const float*)d_in[4];
    const float* bq   = (const float*)d_in[5];
    const float* Wk   = (const float*)d_in[6];
    const float* bk   = (const float*)d_in[7];
    const float* Wv   = (const float*)d_in[8];
    const float* bv   = (const float*)d_in[9];
    const float* Wo   = (const float*)d_in[10];
    const float* bo   = (const float*)d_in[11];
    float* out = (float*)d_out;

    float *Qp, *Kp, *Vp, *AO;
    cudaGetSymbolAddress((void**)&Qp, g_Qp);
    cudaGetSymbolAddress((void**)&Kp, g_Kp);
    cudaGetSymbolAddress((void**)&Vp, g_Vp);
    cudaGetSymbolAddress((void**)&AO, g_AO);

    cudaFuncSetAttribute(attn_kernel,
                         cudaFuncAttributeMaxDynamicSharedMemorySize, ATTN_SMEM);

    // Projections (tensor-core bf16-split GEMMs, 64x64 tiles)
    gemm_bf16_kernel<<<dim3(DM / 64, (BSZ * LQn) / 64), 128>>>(q,  Wq, bq, Qp, BSZ * LQn);
    gemm_bf16_kernel<<<dim3(DM / 64, (BSZ * LKn) / 64), 128>>>(kv, Wk, bk, Kp, BSZ * LKn);
    gemm_bf16_kernel<<<dim3(DM / 64, (BSZ * LKn) / 64), 128>>>(kv, Wv, bv, Vp, BSZ * LKn);
    // Attention (tf32 tensor cores, BQ=128, 2 CTAs/SM)
    attn_kernel<<<dim3(LQn / BQ, NH, BSZ), 256, ATTN_SMEM>>>(gate, mask);
    // Output projection
    gemm_bf16_kernel<<<dim3(DM / 64, (BSZ * LQn) / 64), 128>>>(AO, Wo, bo, out, BSZ * LQn);
}

// round 17
// speedup vs baseline: 1.6999x; 1.1440x over previous
#include <cuda_runtime.h>
#include <cuda_bf16.h>
#include <math.h>
#include <stdint.h>

#define DM 512
#define NH 8
#define DH 64
#define LQn 2048
#define LKn 4096
#define BSZ 2

#define BQ 128
#define BK 64
#define NT (LKn / BK)

// Scratch (allocation-free). g_Kp holds tf32-clean fp32; g_VpT holds tf32-clean
// fp32 TRANSPOSED per (b,h): [b][h][d][key].
__device__ float g_Qp [(size_t)BSZ * LQn * DM];
__device__ float g_Kp [(size_t)BSZ * LKn * DM];
__device__ float g_VpT[(size_t)BSZ * LKn * DM];
__device__ float g_AO [(size_t)BSZ * LQn * DM];

// ---------------------------------------------------------------------------
// MMA + packing primitives
// ---------------------------------------------------------------------------
__device__ __forceinline__ void mma_tf32(float c[4], const uint32_t a[4],
                                         uint32_t b0, uint32_t b1) {
    asm volatile(
        "mma.sync.aligned.m16n8k8.row.col.f32.tf32.tf32.f32 "
        "{%0,%1,%2,%3}, {%4,%5,%6,%7}, {%8,%9}, {%0,%1,%2,%3};"
        : "+f"(c[0]), "+f"(c[1]), "+f"(c[2]), "+f"(c[3])
        : "r"(a[0]), "r"(a[1]), "r"(a[2]), "r"(a[3]), "r"(b0), "r"(b1));
}

__device__ __forceinline__ void mma_bf16(float c[4], const uint32_t a[4],
                                         uint32_t b0, uint32_t b1) {
    asm volatile(
        "mma.sync.aligned.m16n8k16.row.col.f32.bf16.bf16.f32 "
        "{%0,%1,%2,%3}, {%4,%5,%6,%7}, {%8,%9}, {%0,%1,%2,%3};"
        : "+f"(c[0]), "+f"(c[1]), "+f"(c[2]), "+f"(c[3])
        : "r"(a[0]), "r"(a[1]), "r"(a[2]), "r"(a[3]), "r"(b0), "r"(b1));
}

__device__ __forceinline__ uint32_t cvt_tf32(float f) {
    uint32_t u;
    asm("cvt.rna.tf32.f32 %0, %1;" : "=r"(u) : "f"(f));
    return u;
}
__device__ __forceinline__ float cvt_tf32_f(float f) {
    return __uint_as_float(cvt_tf32(f));
}

__device__ __forceinline__ float ex2f(float x) {
    float r;
    asm("ex2.approx.ftz.f32 %0, %1;" : "=f"(r) : "f"(x));
    return r;
}

__device__ __forceinline__ void pack_bf16_hilo(float f0, float f1,
                                               uint32_t& hi, uint32_t& lo) {
    asm("cvt.rn.bf16x2.f32 %0, %1, %2;" : "=r"(hi) : "f"(f1), "f"(f0));
    float h0 = __uint_as_float(hi << 16);
    float h1 = __uint_as_float(hi & 0xffff0000u);
    float r0 = f0 - h0, r1 = f1 - h1;
    asm("cvt.rn.bf16x2.f32 %0, %1, %2;" : "=r"(lo) : "f"(r1), "f"(r0));
}

__device__ __forceinline__ void cp_async16(uint32_t dst, const void* src) {
    asm volatile("cp.async.ca.shared.global [%0], [%1], 16;"
                 :: "r"(dst), "l"(src));
}
__device__ __forceinline__ void cp_commit() {
    asm volatile("cp.async.commit_group;");
}
template <int N>
__device__ __forceinline__ void cp_wait() {
    asm volatile("cp.async.wait_group %0;" :: "n"(N));
}

// ---------------------------------------------------------------------------
// Tensor-core GEMM: C[M,512] = A[M,512] @ W[512,512]^T + bias
// bf16 3-term hi/lo split. CTA: 128 threads / 4 warps; tile 64x64.
// MODE 0: plain fp32 store (Q proj, output proj)
// MODE 1: tf32-rounded store (K proj -> attention consumes bits directly)
// MODE 2: tf32-rounded + transposed store (V proj -> g_VpT [b][h][d][key])
// ---------------------------------------------------------------------------
#define GS 20   // uint32 stride of packed-k rows (16 used + 4 pad)

template <int MODE>
__global__ __launch_bounds__(128)
void gemm_bf16_kernel(const float* __restrict__ A,
                      const float* __restrict__ W,
                      const float* __restrict__ bias,
                      float* __restrict__ C, int M) {
    __shared__ uint32_t AsH[64 * GS], AsL[64 * GS];
    __shared__ uint32_t WsH[64 * GS], WsL[64 * GS];

    const int tid = threadIdx.x;
    const int lane = tid & 31, warp = tid >> 5;
    const int qr = lane >> 2, qc = lane & 3;
    const int n0 = blockIdx.x * 64, m0 = blockIdx.y * 64;

    float acc[8][4];
    #pragma unroll
    for (int nb = 0; nb < 8; nb++)
        #pragma unroll
        for (int i = 0; i < 4; i++) acc[nb][i] = 0.0f;

    for (int k0 = 0; k0 < DM; k0 += 32) {
        __syncthreads();
        #pragma unroll
        for (int p = 0; p < 4; p++) {
            int idx = tid + p * 128;
            int r = idx >> 3, fg = idx & 7;
            float4 av = *(const float4*)(A + (size_t)(m0 + r) * DM + k0 + fg * 4);
            uint32_t h0, l0, h1, l1;
            pack_bf16_hilo(av.x, av.y, h0, l0);
            pack_bf16_hilo(av.z, av.w, h1, l1);
            AsH[r * GS + fg * 2] = h0; AsH[r * GS + fg * 2 + 1] = h1;
            AsL[r * GS + fg * 2] = l0; AsL[r * GS + fg * 2 + 1] = l1;
            float4 wv = *(const float4*)(W + (size_t)(n0 + r) * DM + k0 + fg * 4);
            pack_bf16_hilo(wv.x, wv.y, h0, l0);
            pack_bf16_hilo(wv.z, wv.w, h1, l1);
            WsH[r * GS + fg * 2] = h0; WsH[r * GS + fg * 2 + 1] = h1;
            WsL[r * GS + fg * 2] = l0; WsL[r * GS + fg * 2 + 1] = l1;
        }
        __syncthreads();

        uint32_t ahH[2][4], ahL[2][4];
        #pragma unroll
        for (int kb = 0; kb < 2; kb++) {
            int base = (16 * warp + qr) * GS + kb * 8 + qc;
            ahH[kb][0] = AsH[base];     ahH[kb][1] = AsH[base + 8 * GS];
            ahH[kb][2] = AsH[base + 4]; ahH[kb][3] = AsH[base + 8 * GS + 4];
            ahL[kb][0] = AsL[base];     ahL[kb][1] = AsL[base + 8 * GS];
            ahL[kb][2] = AsL[base + 4]; ahL[kb][3] = AsL[base + 8 * GS + 4];
        }

        #pragma unroll
        for (int nb = 0; nb < 8; nb++) {
            #pragma unroll
            for (int kb = 0; kb < 2; kb++) {
                int wb = (8 * nb + qr) * GS + kb * 8 + qc;
                uint32_t bh0 = WsH[wb], bh1 = WsH[wb + 4];
                uint32_t bl0 = WsL[wb], bl1 = WsL[wb + 4];
                mma_bf16(acc[nb], ahH[kb], bh0, bh1);
                mma_bf16(acc[nb], ahL[kb], bh0, bh1);
                mma_bf16(acc[nb], ahH[kb], bl0, bl1);
            }
        }
    }

    if constexpr (MODE == 2) {
        // Transposed tf32 store: smem-staged, then coalesced STG per d-row.
        __shared__ float Tep[64 * 68];
        #pragma unroll
        for (int nb = 0; nb < 8; nb++) {
            int n = 8 * nb + 2 * qc;
            float2 bv = *(const float2*)(bias + n0 + n);
            int m = 16 * warp + qr;
            Tep[(n + 0) * 68 + m]     = cvt_tf32_f(acc[nb][0] + bv.x);
            Tep[(n + 1) * 68 + m]     = cvt_tf32_f(acc[nb][1] + bv.y);
            Tep[(n + 0) * 68 + m + 8] = cvt_tf32_f(acc[nb][2] + bv.x);
            Tep[(n + 1) * 68 + m + 8] = cvt_tf32_f(acc[nb][3] + bv.y);
        }
        __syncthreads();
        const int bq = m0 >> 12;               // LKn = 4096
        const int key_base = m0 & (LKn - 1);
        #pragma unroll
        for (int p = 0; p < 8; p++) {
            int idx = tid + p * 128;
            int n = idx >> 4, m4 = (idx & 15) * 4;
            float4 v = *(const float4*)&Tep[n * 68 + m4];
            int nf = n0 + n;
            int hh = nf >> 6, dd = nf & 63;
            *(float4*)&C[(((size_t)bq * NH + hh) * DH + dd) * LKn + key_base + m4] = v;
        }
    } else {
        const int row0 = m0 + 16 * warp + qr;
        #pragma unroll
        for (int nb = 0; nb < 8; nb++) {
            int n = n0 + 8 * nb + 2 * qc;
            float2 bv = *(const float2*)(bias + n);
            float2 c01, c23;
            if constexpr (MODE == 1) {
                c01 = make_float2(cvt_tf32_f(acc[nb][0] + bv.x), cvt_tf32_f(acc[nb][1] + bv.y));
                c23 = make_float2(cvt_tf32_f(acc[nb][2] + bv.x), cvt_tf32_f(acc[nb][3] + bv.y));
            } else {
                c01 = make_float2(acc[nb][0] + bv.x, acc[nb][1] + bv.y);
                c23 = make_float2(acc[nb][2] + bv.x, acc[nb][3] + bv.y);
            }
            *(float2*)(C + (size_t)row0 * DM + n) = c01;
            *(float2*)(C + (size_t)(row0 + 8) * DM + n) = c23;
        }
    }
}

// ---------------------------------------------------------------------------
// Tensor-core flash attention. BQ=128 (8 warps x 16 q-rows), BK=64.
// cp.async double-buffered K/V (tf32-clean fp32, no cvt needed in-kernel).
//   S  = Q K^T : tf32 MMA, K smem stride 68 (conflict-free LDS.32).
//   PV = P V   : tf32 MMA permuted-k, V^T smem stride 72 (conflict-free LDS.64).
//   Softmax base-2. Q A-frags staged in per-warp smem (occ 2, 128 regs).
// Dynamic smem: Qf 32KB + 2x(Ks 17KB + Vt 18KB) + gsm 512B = 102.5 KB.
// ---------------------------------------------------------------------------
#define KS 68   // uint32 stride, K rows
#define VS 72   // uint32 stride, V^T rows
#define QF_OFF   0
#define KS_OFF   8192
#define KS_STG   (BK * KS)                 // 4352 words
#define VT_OFF   (KS_OFF + 2 * KS_STG)     // 16896
#define VT_STG   (DH * VS)                 // 4608 words
#define GSM_OFF  (VT_OFF + 2 * VT_STG)     // 26112
#define ATTN_SMEM ((GSM_OFF + 128) * 4)    // 104960 B

__global__ __launch_bounds__(256, 2)
void attn_kernel(const float* __restrict__ gate, const int* __restrict__ mask) {
    extern __shared__ uint32_t smdyn[];
    uint32_t* Qf  = smdyn + QF_OFF;
    float*    gsm = (float*)(smdyn + GSM_OFF);

    const int tid = threadIdx.x;
    const int lane = tid & 31, warp = tid >> 5;
    const int qr = lane >> 2;       // 0..7
    const int qc = lane & 3;        // 0..3
    const int r0 = warp * 16;

    const int q0 = blockIdx.x * BQ;
    const int h = blockIdx.y, b = blockIdx.z;

    const float* Qb  = g_Qp  + ((size_t)b * LQn + q0) * DM + h * DH;
    const float* Kb  = g_Kp  + (size_t)b * LKn * DM + h * DH;
    const float* VtG = g_VpT + ((size_t)b * NH + h) * DH * LKn;   // [d][key]
    const float* gb  = gate + (size_t)b * LKn;
    const int*   mb  = mask + (size_t)b * LKn;

    const uint32_t ks_base = (uint32_t)__cvta_generic_to_shared(smdyn + KS_OFF);
    const uint32_t vt_base = (uint32_t)__cvta_generic_to_shared(smdyn + VT_OFF);

    // ---- prologue: stream tile 0 via cp.async ----
    #pragma unroll
    for (int p = 0; p < 4; p++) {
        int idx = tid + p * 256;
        int r = idx >> 4, cg = idx & 15;
        cp_async16(ks_base + r * (KS * 4) + cg * 16,
                   Kb + (size_t)r * DM + cg * 4);
    }
    #pragma unroll
    for (int p = 0; p < 4; p++) {
        int idx = tid + p * 256;
        int d = idx >> 4, ch = idx & 15;
        cp_async16(vt_base + d * (VS * 4) + ch * 16,
                   VtG + (size_t)d * LKn + ch * 4);
    }
    cp_commit();
    if (tid < BK) {
        float g = __log2f(fmaxf(gb[tid], 1e-6f));
        gsm[tid] = (mb[tid] == 0) ? -1e30f : g;
    }

    // ---- Q A-fragments (scale*log2e folded) -> own-slot smem buffer ----
    {
        const float QSC = 0.125f * 1.44269504088896f;
        const float* Qr0 = Qb + (size_t)(r0 + qr) * DM;
        const float* Qr1 = Qb + (size_t)(r0 + qr + 8) * DM;
        #pragma unroll
        for (int kb = 0; kb < 8; kb++) {
            uint4 u;
            u.x = cvt_tf32(Qr0[8 * kb + qc] * QSC);
            u.y = cvt_tf32(Qr1[8 * kb + qc] * QSC);
            u.z = cvt_tf32(Qr0[8 * kb + qc + 4] * QSC);
            u.w = cvt_tf32(Qr1[8 * kb + qc + 4] * QSC);
            *(uint4*)&Qf[((warp * 8 + kb) * 32 + lane) * 4] = u;
        }
    }

    float m_a = -1e30f, m_b = -1e30f, l_a = 0.0f, l_b = 0.0f;
    float oacc[8][4];
    #pragma unroll
    for (int nb = 0; nb < 8; nb++)
        #pragma unroll
        for (int i = 0; i < 4; i++) oacc[nb][i] = 0.0f;

    #pragma unroll 1
    for (int it = 0; it < NT; it++) {
        const int cur = it & 1;
        const bool produce = (it + 1 < NT);

        // ---- stream tile t+1 into the other stage, then wait for tile t ----
        if (produce) {
            const int nxt = cur ^ 1;
            const int k1 = (it + 1) * BK;
            const uint32_t kdst = ks_base + nxt * (KS_STG * 4);
            #pragma unroll
            for (int p = 0; p < 4; p++) {
                int idx = tid + p * 256;
                int r = idx >> 4, cg = idx & 15;
                cp_async16(kdst + r * (KS * 4) + cg * 16,
                           Kb + (size_t)(k1 + r) * DM + cg * 4);
            }
            const uint32_t vdst = vt_base + nxt * (VT_STG * 4);
            #pragma unroll
            for (int p = 0; p < 4; p++) {
                int idx = tid + p * 256;
                int d = idx >> 4, ch = idx & 15;
                cp_async16(vdst + d * (VS * 4) + ch * 16,
                           VtG + (size_t)d * LKn + k1 + ch * 4);
            }
            cp_commit();
            if (tid < BK) {
                float g = __log2f(fmaxf(gb[k1 + tid], 1e-6f));
                gsm[nxt * 64 + tid] = (mb[k1 + tid] == 0) ? -1e30f : g;
            }
            cp_wait<1>();
        } else {
            cp_wait<0>();
        }
        __syncthreads();   // tile t visible to all; all warps past consume(t-1)

        const uint32_t* Ks = smdyn + KS_OFF + cur * KS_STG;
        const uint32_t* Vt = smdyn + VT_OFF + cur * VT_STG;
        const float*    gc = gsm + cur * 64;

        // ---- S = Q K^T (tf32 MMA; kb-outer, qa streamed from smem) ----
        float sacc[8][4];
        #pragma unroll
        for (int nb = 0; nb < 8; nb++)
            #pragma unroll
            for (int i = 0; i < 4; i++) sacc[nb][i] = 0.0f;
        #pragma unroll
        for (int kb = 0; kb < 8; kb++) {
            uint4 q4 = *(const uint4*)&Qf[((warp * 8 + kb) * 32 + lane) * 4];
            uint32_t qa[4] = { q4.x, q4.y, q4.z, q4.w };
            #pragma unroll
            for (int nb = 0; nb < 8; nb++) {
                int row = 8 * nb + qr;
                uint32_t b0 = Ks[row * KS + 8 * kb + qc];
                uint32_t b1 = Ks[row * KS + 8 * kb + qc + 4];
                mma_tf32(sacc[nb], qa, b0, b1);
            }
        }

        // ---- gate + mask, online softmax (base-2) ----
        float mxa = -1e30f, mxb = -1e30f;
        #pragma unroll
        for (int nb = 0; nb < 8; nb++) {
            float g0 = gc[8 * nb + 2 * qc];
            float g1 = gc[8 * nb + 2 * qc + 1];
            sacc[nb][0] += g0; sacc[nb][1] += g1;
            sacc[nb][2] += g0; sacc[nb][3] += g1;
            mxa = fmaxf(mxa, fmaxf(sacc[nb][0], sacc[nb][1]));
            mxb = fmaxf(mxb, fmaxf(sacc[nb][2], sacc[nb][3]));
        }
        mxa = fmaxf(mxa, __shfl_xor_sync(0xffffffffu, mxa, 1));
        mxa = fmaxf(mxa, __shfl_xor_sync(0xffffffffu, mxa, 2));
        mxb = fmaxf(mxb, __shfl_xor_sync(0xffffffffu, mxb, 1));
        mxb = fmaxf(mxb, __shfl_xor_sync(0xffffffffu, mxb, 2));

        float mna = fmaxf(m_a, mxa), mnb = fmaxf(m_b, mxb);
        float alpha_a = ex2f(m_a - mna), alpha_b = ex2f(m_b - mnb);
        m_a = mna; m_b = mnb;

        float suma = 0.0f, sumb = 0.0f;
        #pragma unroll
        for (int nb = 0; nb < 8; nb++) {
            sacc[nb][0] = ex2f(sacc[nb][0] - m_a);
            sacc[nb][1] = ex2f(sacc[nb][1] - m_a);
            sacc[nb][2] = ex2f(sacc[nb][2] - m_b);
            sacc[nb][3] = ex2f(sacc[nb][3] - m_b);
            suma += sacc[nb][0] + sacc[nb][1];
            sumb += sacc[nb][2] + sacc[nb][3];
        }
        suma += __shfl_xor_sync(0xffffffffu, suma, 1);
        suma += __shfl_xor_sync(0xffffffffu, suma, 2);
        sumb += __shfl_xor_sync(0xffffffffu, sumb, 1);
        sumb += __shfl_xor_sync(0xffffffffu, sumb, 2);
        l_a = l_a * alpha_a + suma;
        l_b = l_b * alpha_b + sumb;

        #pragma unroll
        for (int nb = 0; nb < 8; nb++) {
            oacc[nb][0] *= alpha_a; oacc[nb][1] *= alpha_a;
            oacc[nb][2] *= alpha_b; oacc[nb][3] *= alpha_b;
        }

        // ---- O += P V (tf32 MMA, permuted-k; B = adjacent key pair LDS.64) ----
        #pragma unroll
        for (int kb = 0; kb < 8; kb++) {
            uint32_t pa[4];
            pa[0] = cvt_tf32(sacc[kb][0]);
            pa[1] = cvt_tf32(sacc[kb][2]);
            pa[2] = cvt_tf32(sacc[kb][1]);
            pa[3] = cvt_tf32(sacc[kb][3]);
            int kcol = 8 * kb + 2 * qc;
            #pragma unroll
            for (int nb = 0; nb < 8; nb++) {
                int d = 8 * nb + qr;
                uint2 bv = *(const uint2*)&Vt[d * VS + kcol];
                mma_tf32(oacc[nb], pa, bv.x, bv.y);
            }
        }
        __syncthreads();   // consume(t) done: stage may be overwritten next iter
    }

    // ---- epilogue ----
    float inva = 1.0f / l_a, invb = 1.0f / l_b;
    float* Ob = g_AO + ((size_t)b * LQn + q0 + r0 + qr) * DM + h * DH;
    #pragma unroll
    for (int nb = 0; nb < 8; nb++) {
        float2 va = make_float2(oacc[nb][0] * inva, oacc[nb][1] * inva);
        *(float2*)(Ob + 8 * nb + 2 * qc) = va;
        float2 vb2 = make_float2(oacc[nb][2] * invb, oacc[nb][3] * invb);
        *(float2*)(Ob + (size_t)8 * DM + 8 * nb + 2 * qc) = vb2;
    }
}

extern "C" void kernel_launch(void* const* d_in, const int* in_sizes, int n_in,
                              void* d_out, int out_size) {
    const float* q    = (const float*)d_in[0];
    const float* kv   = (const float*)d_in[1];
    const float* gate = (const float*)d_in[2];
    const int*   mask = (const int*)d_in[3];
    const float* Wq   = (const float*)d_in[4];
    const float* bq   = (const float*)d_in[5];
    const float* Wk   = (const float*)d_in[6];
    const float* bk   = (const float*)d_in[7];
    const float* Wv   = (const float*)d_in[8];
    const float* bv   = (const float*)d_in[9];
    const float* Wo   = (const float*)d_in[10];
    const float* bo   = (const float*)d_in[11];
    float* out = (float*)d_out;

    float *Qp, *Kp, *VpT, *AO;
    cudaGetSymbolAddress((void**)&Qp,  g_Qp);
    cudaGetSymbolAddress((void**)&Kp,  g_Kp);
    cudaGetSymbolAddress((void**)&VpT, g_VpT);
    cudaGetSymbolAddress((void**)&AO,  g_AO);

    cudaFuncSetAttribute(attn_kernel,
                         cudaFuncAttributeMaxDynamicSharedMemorySize, ATTN_SMEM);

    // Projections (tensor-core bf16-split GEMMs, 64x64 tiles)
    gemm_bf16_kernel<0><<<dim3(DM / 64, (BSZ * LQn) / 64), 128>>>(q,  Wq, bq, Qp,  BSZ * LQn);
    gemm_bf16_kernel<1><<<dim3(DM / 64, (BSZ * LKn) / 64), 128>>>(kv, Wk, bk, Kp,  BSZ * LKn);
    gemm_bf16_kernel<2><<<dim3(DM / 64, (BSZ * LKn) / 64), 128>>>(kv, Wv, bv, VpT, BSZ * LKn);
    // Attention (tf32 tensor cores, cp.async double-buffered, 2 CTAs/SM)
    attn_kernel<<<dim3(LQn / BQ, NH, BSZ), 256, ATTN_SMEM>>>(gate, mask);
    // Output projection
    gemm_bf16_kernel<0><<<dim3(DM / 64, (BSZ * LQn) / 64), 128>>>(AO, Wo, bo, out, BSZ * LQn);
}